// round 9
// baseline (speedup 1.0000x reference)
#include <cuda_runtime.h>
#include <cuda_fp16.h>

// PointWarping2 — Nadaraya-Watson Gaussian regression (exact f32 math).
// Source-pair f32x2 packing + 4 queries per thread: each smem tile load is
// amortized over 4 queries (halves LDS/MIO traffic per src*query vs R7).
// Split-K MSPLIT=32, fused last-block reduction (counter mod trick).
//
// w' = ex2( q . a_xyz + a_w ), a = (2L*y, -L*|y|^2), L = log2(e)/s^2
// (per-query factor 2^{L|q|^2} cancels in num/den — exact).

#define Bx 2
#define N1x 8192
#define N2x 8192
#define NQ (Bx * N2x)           // 16384 queries
#define MSPLIT 32
#define TILE 256                 // sources per split
#define PAIRS (TILE / 2)         // 128 packed source-pairs per tile
#define BLK 128
#define QPT 4                    // queries per thread
#define QPB (BLK * QPT)          // 512 queries per block
#define GRIDX (NQ / QPB)         // 32 query columns

typedef unsigned long long ull;

__device__ float4 g_partial[MSPLIT * NQ];
__device__ unsigned g_count[GRIDX];   // zero-init at load; mod trick, never reset

__device__ __forceinline__ float ex2f(float x) {
    float y;
    asm("ex2.approx.ftz.f32 %0, %1;" : "=f"(y) : "f"(x));
    return y;
}
__device__ __forceinline__ ull fma2(ull a, ull b, ull c) {
    ull d;
    asm("fma.rn.f32x2 %0, %1, %2, %3;" : "=l"(d) : "l"(a), "l"(b), "l"(c));
    return d;
}
__device__ __forceinline__ ull add2(ull a, ull b) {
    ull d;
    asm("add.rn.f32x2 %0, %1, %2;" : "=l"(d) : "l"(a), "l"(b));
    return d;
}
__device__ __forceinline__ ull pack2(float lo, float hi) {
    ull d;
    asm("mov.b64 %0, {%1, %2};" : "=l"(d) : "f"(lo), "f"(hi));
    return d;
}
__device__ __forceinline__ void unpack2(ull v, float& lo, float& hi) {
    asm("mov.b64 {%0, %1}, %2;" : "=f"(lo), "=f"(hi) : "l"(v));
}

// resol_factor may arrive as int32 or float32 bits; disambiguate.
__device__ __forceinline__ float read_scale(const void* p) {
    int iv = *(const int*)p;
    float f;
    if (iv > 0 && iv < 100000) f = (float)iv;
    else f = __int_as_float(iv);
    return 1.0f * f;  // INITIAL_RADIUS = 1.0
}

__global__ __launch_bounds__(BLK) void main_kernel(
    const float* __restrict__ xyz1, const float* __restrict__ xyz2,
    const float* __restrict__ flow1, const void* __restrict__ resol,
    float* __restrict__ out) {
    __shared__ float4 s0[PAIRS];   // (ax0,ax1, ay0,ay1)
    __shared__ float4 s1[PAIRS];   // (az0,az1, aw0,aw1)
    __shared__ float4 s2[PAIRS];   // (fx0,fx1, fy0,fy1)
    __shared__ float2 s3[PAIRS];   // (fz0,fz1)
    __shared__ unsigned s_old;

    int qbase = blockIdx.x * QPB;          // block stays within one batch
    int b = qbase >> 13;

    float scale = read_scale(resol);
    float L = 1.4426950408889634f / (scale * scale);
    float t2 = 2.0f * L;

    // ---- fused prep: build packed source tile from raw inputs ----
    const float* x1b = xyz1 + b * 3 * N1x;
    const float* f1b = flow1 + b * 3 * N1x;
    int m0 = blockIdx.y * TILE;
    #pragma unroll
    for (int i = threadIdx.x; i < PAIRS; i += BLK) {
        int m = m0 + 2 * i;
        float2 xx = *(const float2*)(x1b + m);
        float2 xy = *(const float2*)(x1b + N1x + m);
        float2 xz = *(const float2*)(x1b + 2 * N1x + m);
        float2 fx = *(const float2*)(f1b + m);
        float2 fy = *(const float2*)(f1b + N1x + m);
        float2 fz = *(const float2*)(f1b + 2 * N1x + m);
        float yx0 = xx.x + fx.x, yx1 = xx.y + fx.y;
        float yy0 = xy.x + fy.x, yy1 = xy.y + fy.y;
        float yz0 = xz.x + fz.x, yz1 = xz.y + fz.y;
        s0[i] = make_float4(t2 * yx0, t2 * yx1, t2 * yy0, t2 * yy1);
        s1[i] = make_float4(t2 * yz0, t2 * yz1,
                            -L * (yx0 * yx0 + yy0 * yy0 + yz0 * yz0),
                            -L * (yx1 * yx1 + yy1 * yy1 + yz1 * yz1));
        s2[i] = make_float4(fx.x, fx.y, fy.x, fy.y);
        s3[i] = make_float2(fz.x, fz.y);
    }

    // ---- query registers (QPT queries per thread, broadcast-packed) ----
    const float* x2b = xyz2 + b * 3 * N2x;
    ull qx2[QPT], qy2[QPT], qz2[QPT];
    #pragma unroll
    for (int k = 0; k < QPT; k++) {
        int n = (qbase + threadIdx.x + k * BLK) & (N2x - 1);
        float qx = x2b[n], qy = x2b[N2x + n], qz = x2b[2 * N2x + n];
        qx2[k] = pack2(qx, qx);
        qy2[k] = pack2(qy, qy);
        qz2[k] = pack2(qz, qz);
    }

    __syncthreads();

    const ulonglong2* u0 = (const ulonglong2*)s0;
    const ulonglong2* u1 = (const ulonglong2*)s1;
    const ulonglong2* u2 = (const ulonglong2*)s2;
    const ull*        u3 = (const ull*)s3;

    ull nx[QPT], ny[QPT], nz[QPT], dn[QPT];
    #pragma unroll
    for (int k = 0; k < QPT; k++) { nx[k] = ny[k] = nz[k] = dn[k] = 0; }

    #pragma unroll 4
    for (int j = 0; j < PAIRS; j++) {
        ulonglong2 a01 = u0[j];   // ax2, ay2
        ulonglong2 a23 = u1[j];   // az2, aw2
        ulonglong2 f01 = u2[j];   // fx2, fy2
        ull        fz2 = u3[j];
        #pragma unroll
        for (int k = 0; k < QPT; k++) {
            ull arg = fma2(qx2[k], a01.x,
                      fma2(qy2[k], a01.y,
                      fma2(qz2[k], a23.x, a23.y)));
            float al, ah;
            unpack2(arg, al, ah);
            ull w = pack2(ex2f(al), ex2f(ah));
            nx[k] = fma2(w, f01.x, nx[k]);
            ny[k] = fma2(w, f01.y, ny[k]);
            nz[k] = fma2(w, fz2,   nz[k]);
            dn[k] = add2(dn[k], w);
        }
    }

    #pragma unroll
    for (int k = 0; k < QPT; k++) {
        int q = qbase + threadIdx.x + k * BLK;
        float a, c;
        float4 r;
        unpack2(nx[k], a, c); r.x = a + c;
        unpack2(ny[k], a, c); r.y = a + c;
        unpack2(nz[k], a, c); r.z = a + c;
        unpack2(dn[k], a, c); r.w = a + c;
        g_partial[blockIdx.y * NQ + q] = r;
    }

    // ---- last-block reduction for this query column ----
    __threadfence();
    if (threadIdx.x == 0)
        s_old = atomicAdd(&g_count[blockIdx.x], 1u);
    __syncthreads();
    if ((s_old % MSPLIT) != (MSPLIT - 1)) return;

    // Last of the MSPLIT splits for query column blockIdx.x:
    // register-thrifty chunked reduction, 8 loads in flight.
    const float* x2o = xyz2 + b * 3 * N2x;
    float* ob = out + b * 3 * N2x;
    #pragma unroll
    for (int k = 0; k < QPT; k++) {
        int q = qbase + threadIdx.x + k * BLK;
        float accx = 0.f, accy = 0.f, accz = 0.f, accw = 0.f;
        #pragma unroll
        for (int c = 0; c < MSPLIT / 8; c++) {
            float4 t[8];
            #pragma unroll
            for (int s = 0; s < 8; s++) t[s] = g_partial[(c * 8 + s) * NQ + q];
            #pragma unroll
            for (int s = 0; s < 8; s++) {
                accx += t[s].x; accy += t[s].y; accz += t[s].z; accw += t[s].w;
            }
        }
        int n = q & (N2x - 1);
        float inv = 1.0f / accw;
        ob[0 * N2x + n] = x2o[0 * N2x + n] - accx * inv;
        ob[1 * N2x + n] = x2o[1 * N2x + n] - accy * inv;
        ob[2 * N2x + n] = x2o[2 * N2x + n] - accz * inv;
    }
}

extern "C" void kernel_launch(void* const* d_in, const int* in_sizes, int n_in,
                              void* d_out, int out_size) {
    const float* xyz1  = (const float*)d_in[0];
    const float* xyz2  = (const float*)d_in[1];
    const float* flow1 = (const float*)d_in[2];
    const void*  resol = d_in[3];
    float* out = (float*)d_out;

    dim3 grid(GRIDX, MSPLIT);   // 32 x 32 = 1024 blocks
    main_kernel<<<grid, BLK>>>(xyz1, xyz2, flow1, resol, out);
}

// round 10
// speedup vs baseline: 1.8072x; 1.8072x over previous
#include <cuda_runtime.h>
#include <cuda_fp16.h>

// PointWarping2 — Nadaraya-Watson Gaussian regression, fp16x2 inner loop.
// HFMA2/HADD2 are full-rate (2 values per rt-2 op) vs f32x2 FFMA at rt-4:
// halves FMA-pipe cycles AND MUFU ops per (source, query).
//   arg  = qx*ax + qy*ay + qz*az + (aw + cn)      [half2, 2 sources packed]
//   w    = ex2.approx.f16x2(arg)
//   accum in half2 (even/odd source lanes), promoted to f32 every 32 pairs.
// Per-query bias cn rounds identically for all sources -> cancels in num/den.
// Split-K MSPLIT=16, fused last-block reduction (counter mod trick).

#define Bx 2
#define N1x 8192
#define N2x 8192
#define NQ (Bx * N2x)           // 16384 queries
#define MSPLIT 16
#define TILE 512                 // sources per split
#define PAIRS (TILE / 2)         // 256 packed source-pairs per tile
#define BLK 128
#define QPT 2                    // queries per thread
#define QPB (BLK * QPT)          // 256 queries per block
#define GRIDX (NQ / QPB)         // 64 query columns
#define KCH 32                   // pairs per fp16 accumulation chunk

__device__ float4 g_partial[MSPLIT * NQ];
__device__ unsigned g_count[GRIDX];   // zero-init at load; mod trick, never reset

__device__ __forceinline__ half2 h2ex2(half2 x) {
    unsigned xu = *reinterpret_cast<unsigned*>(&x);
    unsigned yu;
    asm("ex2.approx.f16x2 %0, %1;" : "=r"(yu) : "r"(xu));
    half2 y;
    *reinterpret_cast<unsigned*>(&y) = yu;
    return y;
}
__device__ __forceinline__ half2 u2h2(unsigned u) {
    half2 h;
    *reinterpret_cast<unsigned*>(&h) = u;
    return h;
}
__device__ __forceinline__ unsigned h22u(half2 h) {
    return *reinterpret_cast<unsigned*>(&h);
}

// resol_factor may arrive as int32 or float32 bits; disambiguate.
__device__ __forceinline__ float read_scale(const void* p) {
    int iv = *(const int*)p;
    float f;
    if (iv > 0 && iv < 100000) f = (float)iv;
    else f = __int_as_float(iv);
    return 1.0f * f;  // INITIAL_RADIUS = 1.0
}

__global__ __launch_bounds__(BLK) void main_kernel(
    const float* __restrict__ xyz1, const float* __restrict__ xyz2,
    const float* __restrict__ flow1, const void* __restrict__ resol,
    float* __restrict__ out) {
    __shared__ uint4 sA[PAIRS];   // (ax01, ay01, az01, aw01) half2 each
    __shared__ uint4 sF[PAIRS];   // (fx01, fy01, fz01, 0)    half2 each
    __shared__ unsigned s_old;

    int qbase = blockIdx.x * QPB;          // block stays within one batch
    int b = qbase >> 13;

    float scale = read_scale(resol);
    float L = 1.4426950408889634f / (scale * scale);
    float t2 = 2.0f * L;

    // ---- fused prep: build fp16-packed source tile (math in f32) ----
    const float* x1b = xyz1 + b * 3 * N1x;
    const float* f1b = flow1 + b * 3 * N1x;
    int m0 = blockIdx.y * TILE;
    #pragma unroll
    for (int i = threadIdx.x; i < PAIRS; i += BLK) {
        int m = m0 + 2 * i;
        float2 xx = *(const float2*)(x1b + m);
        float2 xy = *(const float2*)(x1b + N1x + m);
        float2 xz = *(const float2*)(x1b + 2 * N1x + m);
        float2 fx = *(const float2*)(f1b + m);
        float2 fy = *(const float2*)(f1b + N1x + m);
        float2 fz = *(const float2*)(f1b + 2 * N1x + m);
        float yx0 = xx.x + fx.x, yx1 = xx.y + fx.y;
        float yy0 = xy.x + fy.x, yy1 = xy.y + fy.y;
        float yz0 = xz.x + fz.x, yz1 = xz.y + fz.y;
        float aw0 = -L * (yx0 * yx0 + yy0 * yy0 + yz0 * yz0);
        float aw1 = -L * (yx1 * yx1 + yy1 * yy1 + yz1 * yz1);
        sA[i] = make_uint4(
            h22u(__floats2half2_rn(t2 * yx0, t2 * yx1)),
            h22u(__floats2half2_rn(t2 * yy0, t2 * yy1)),
            h22u(__floats2half2_rn(t2 * yz0, t2 * yz1)),
            h22u(__floats2half2_rn(aw0, aw1)));
        sF[i] = make_uint4(
            h22u(__floats2half2_rn(fx.x, fx.y)),
            h22u(__floats2half2_rn(fy.x, fy.y)),
            h22u(__floats2half2_rn(fz.x, fz.y)), 0u);
    }

    // ---- query registers (QPT queries per thread, fp16 broadcast pairs) ----
    const float* x2b = xyz2 + b * 3 * N2x;
    half2 qxh[QPT], qyh[QPT], qzh[QPT], cnh[QPT];
    #pragma unroll
    for (int k = 0; k < QPT; k++) {
        int n = (qbase + threadIdx.x + k * BLK) & (N2x - 1);
        float qx = x2b[n], qy = x2b[N2x + n], qz = x2b[2 * N2x + n];
        float cn = -L * (qx * qx + qy * qy + qz * qz);
        qxh[k] = __float2half2_rn(qx);
        qyh[k] = __float2half2_rn(qy);
        qzh[k] = __float2half2_rn(qz);
        cnh[k] = __float2half2_rn(cn);
    }

    __syncthreads();

    float accx[QPT], accy[QPT], accz[QPT], accd[QPT];
    #pragma unroll
    for (int k = 0; k < QPT; k++) accx[k] = accy[k] = accz[k] = accd[k] = 0.f;

    for (int c0 = 0; c0 < PAIRS; c0 += KCH) {
        half2 hx[QPT], hy[QPT], hz[QPT], hd[QPT];
        half2 hzero = __float2half2_rn(0.f);
        #pragma unroll
        for (int k = 0; k < QPT; k++) { hx[k] = hy[k] = hz[k] = hd[k] = hzero; }

        #pragma unroll 8
        for (int j = c0; j < c0 + KCH; j++) {
            uint4 a = sA[j];
            uint4 f = sF[j];
            half2 ax = u2h2(a.x), ay = u2h2(a.y), az = u2h2(a.z), aw = u2h2(a.w);
            half2 fx = u2h2(f.x), fy = u2h2(f.y), fz = u2h2(f.z);
            #pragma unroll
            for (int k = 0; k < QPT; k++) {
                half2 t = __hadd2(aw, cnh[k]);
                t = __hfma2(qzh[k], az, t);
                t = __hfma2(qyh[k], ay, t);
                t = __hfma2(qxh[k], ax, t);
                half2 w = h2ex2(t);
                hx[k] = __hfma2(w, fx, hx[k]);
                hy[k] = __hfma2(w, fy, hy[k]);
                hz[k] = __hfma2(w, fz, hz[k]);
                hd[k] = __hadd2(hd[k], w);
            }
        }
        // promote chunk subtotals to f32
        #pragma unroll
        for (int k = 0; k < QPT; k++) {
            float2 v;
            v = __half22float2(hx[k]); accx[k] += v.x + v.y;
            v = __half22float2(hy[k]); accy[k] += v.x + v.y;
            v = __half22float2(hz[k]); accz[k] += v.x + v.y;
            v = __half22float2(hd[k]); accd[k] += v.x + v.y;
        }
    }

    #pragma unroll
    for (int k = 0; k < QPT; k++) {
        int q = qbase + threadIdx.x + k * BLK;
        g_partial[blockIdx.y * NQ + q] =
            make_float4(accx[k], accy[k], accz[k], accd[k]);
    }

    // ---- last-block reduction for this query column ----
    __threadfence();
    if (threadIdx.x == 0)
        s_old = atomicAdd(&g_count[blockIdx.x], 1u);
    __syncthreads();
    if ((s_old % MSPLIT) != (MSPLIT - 1)) return;

    // Last of the MSPLIT splits for query column blockIdx.x:
    // register-thrifty chunked reduction, 8 loads in flight.
    const float* x2o = xyz2 + b * 3 * N2x;
    float* ob = out + b * 3 * N2x;
    #pragma unroll
    for (int k = 0; k < QPT; k++) {
        int q = qbase + threadIdx.x + k * BLK;
        float rx = 0.f, ry = 0.f, rz = 0.f, rw = 0.f;
        #pragma unroll
        for (int c = 0; c < MSPLIT / 8; c++) {
            float4 t[8];
            #pragma unroll
            for (int s = 0; s < 8; s++) t[s] = g_partial[(c * 8 + s) * NQ + q];
            #pragma unroll
            for (int s = 0; s < 8; s++) {
                rx += t[s].x; ry += t[s].y; rz += t[s].z; rw += t[s].w;
            }
        }
        int n = q & (N2x - 1);
        float inv = 1.0f / rw;
        ob[0 * N2x + n] = x2o[0 * N2x + n] - rx * inv;
        ob[1 * N2x + n] = x2o[1 * N2x + n] - ry * inv;
        ob[2 * N2x + n] = x2o[2 * N2x + n] - rz * inv;
    }
}

extern "C" void kernel_launch(void* const* d_in, const int* in_sizes, int n_in,
                              void* d_out, int out_size) {
    const float* xyz1  = (const float*)d_in[0];
    const float* xyz2  = (const float*)d_in[1];
    const float* flow1 = (const float*)d_in[2];
    const void*  resol = d_in[3];
    float* out = (float*)d_out;

    dim3 grid(GRIDX, MSPLIT);   // 64 x 16 = 1024 blocks
    main_kernel<<<grid, BLK>>>(xyz1, xyz2, flow1, resol, out);
}